// round 6
// baseline (speedup 1.0000x reference)
#include <cuda_runtime.h>
#include <cuda_bf16.h>

// InvertiblePWL, single fused kernel, single-wave grid:
//   out = eps * A[idx] + B[idx],  idx = clamp(floor((eps+5)*9.9)+1, 0, 100)
//   A[i] = exp(p[i]) + 0.001
//   B[i] = (b0 + pref_excl[i]) - points[max(i-1,0)] * A[i]
//   pref_excl[i] = sum_{j=1..i-1} int_len*(exp(p[j])+0.001)
// Warp 0 builds the table with ONE warp scan (each lane owns 4 contiguous
// indices); all warps front-batch 4 LDG.128 before the barrier.

#define N_BINS 100
#define TPB    256
#define V      4            // float4s per thread
#define GRID   1184         // 8 CTAs/SM * 148 SMs -> exactly one wave

__global__ void __launch_bounds__(TPB, 8)
pwl_kernel(const float4* __restrict__ eps,
           const float*  __restrict__ p,
           const float*  __restrict__ b,
           const float*  __restrict__ points,
           float4* __restrict__ out, int n4) {
    __shared__ float2 sAB[N_BINS + 1];

    const int t = threadIdx.x;

    // ---- Warp 0: build table. Lane l owns indices 4l..4l+3 (0..127).
    if (t < 32) {
        const float int_len = 10.0f / 99.0f;
        const int i0 = 4 * t;

        // Front-batched independent loads.
        const float b0 = b[0];
        float pv[4], pts[4];
#pragma unroll
        for (int k = 0; k < 4; k++) {
            const int idx = i0 + k;
            pv[k]  = (idx <= N_BINS) ? p[idx] : 0.0f;
            const int s = (idx > 0) ? (idx - 1) : 0;
            pts[k] = (idx <= N_BINS) ? points[s] : 0.0f;
        }

        float a[4], d[4];
#pragma unroll
        for (int k = 0; k < 4; k++) {
            const int idx = i0 + k;
            a[k] = expf(pv[k]) + 0.001f;
            d[k] = (idx >= 1 && idx <= N_BINS - 1) ? int_len * a[k] : 0.0f;
        }

        // Local inclusive prefix within the lane's 4 values.
        float l1 = d[0] + d[1];
        float lsum = l1 + d[2] + d[3];

        // One inclusive warp scan over the lane sums.
        float incl = lsum;
#pragma unroll
        for (int o = 1; o < 32; o <<= 1) {
            float u = __shfl_up_sync(0xFFFFFFFFu, incl, o);
            if (t >= o) incl += u;
        }
        const float lane_excl = incl - lsum;

        // Exclusive prefix at each index: sum of d[1..idx-1].
        float ex[4];
        ex[0] = lane_excl;
        ex[1] = lane_excl + d[0];
        ex[2] = lane_excl + l1;
        ex[3] = lane_excl + l1 + d[2];

#pragma unroll
        for (int k = 0; k < 4; k++) {
            const int idx = i0 + k;
            if (idx <= N_BINS)
                sAB[idx] = make_float2(a[k], (b0 + ex[k]) - pts[k] * a[k]);
        }
    }

    // ---- Front-batched eps loads (16 lines in flight per warp).
    const int base = blockIdx.x * (TPB * V) + t;
    float4 e[V];
#pragma unroll
    for (int j = 0; j < V; j++) {
        const int i = base + j * TPB;
        if (i < n4) e[j] = eps[i];
    }

    __syncthreads();   // table visible; loads stay in flight across BAR

    // ---- Gather + FMA + store.
    const float inv_len = 99.0f / 10.0f;
#pragma unroll
    for (int j = 0; j < V; j++) {
        const int i = base + j * TPB;
        if (i >= n4) continue;
        float4 r;
        {
            int ix = __float2int_rd(fmaf(e[j].x, inv_len, 49.5f)) + 1;
            ix = max(0, min(ix, N_BINS));
            const float2 ab = sAB[ix];
            r.x = fmaf(e[j].x, ab.x, ab.y);
        }
        {
            int ix = __float2int_rd(fmaf(e[j].y, inv_len, 49.5f)) + 1;
            ix = max(0, min(ix, N_BINS));
            const float2 ab = sAB[ix];
            r.y = fmaf(e[j].y, ab.x, ab.y);
        }
        {
            int ix = __float2int_rd(fmaf(e[j].z, inv_len, 49.5f)) + 1;
            ix = max(0, min(ix, N_BINS));
            const float2 ab = sAB[ix];
            r.z = fmaf(e[j].z, ab.x, ab.y);
        }
        {
            int ix = __float2int_rd(fmaf(e[j].w, inv_len, 49.5f)) + 1;
            ix = max(0, min(ix, N_BINS));
            const float2 ab = sAB[ix];
            r.w = fmaf(e[j].w, ab.x, ab.y);
        }
        out[i] = r;
    }
}

extern "C" void kernel_launch(void* const* d_in, const int* in_sizes, int n_in,
                              void* d_out, int out_size) {
    const float* eps    = (const float*)d_in[0];   // [4000000]
    const float* p      = (const float*)d_in[1];   // [101]
    const float* b      = (const float*)d_in[2];   // [1]
    const float* points = (const float*)d_in[3];   // [100]
    float* out = (float*)d_out;

    const int n4 = out_size / 4;                   // 1,000,000
    pwl_kernel<<<GRID, TPB>>>((const float4*)eps, p, b, points,
                              (float4*)out, n4);
}

// round 7
// speedup vs baseline: 1.2148x; 1.2148x over previous
#include <cuda_runtime.h>
#include <cuda_bf16.h>

// InvertiblePWL, persistent single-wave kernel with pipelined grid-stride loop:
//   out = eps * A[idx] + B[idx],  idx = clamp(floor((eps+5)*9.9)+1, 0, 100)
//   A[i] = exp(p[i]) + 0.001
//   B[i] = (b0 + pref_excl[i]) - points[max(i-1,0)] * A[i]
// Warp 0 builds the 101-entry table once per CTA (single warp scan); the main
// loop always has the next LDG.128 in flight while processing the current one.

#define N_BINS 100
#define TPB    256
#define GRID   1184         // 8 CTAs/SM * 148 SMs -> one persistent wave

__global__ void __launch_bounds__(TPB, 8)
pwl_kernel(const float4* __restrict__ eps,
           const float*  __restrict__ p,
           const float*  __restrict__ b,
           const float*  __restrict__ points,
           float4* __restrict__ out, int n4) {
    __shared__ float2 sAB[N_BINS + 1];

    const int t = threadIdx.x;

    // ---- Warp 0: build table. Lane l owns indices 4l..4l+3 (0..127).
    if (t < 32) {
        const float int_len = 10.0f / 99.0f;
        const int i0 = 4 * t;
        const float b0 = b[0];

        float pv[4], pts[4];
#pragma unroll
        for (int k = 0; k < 4; k++) {
            const int idx = i0 + k;
            pv[k]  = (idx <= N_BINS) ? p[idx] : 0.0f;
            const int s = (idx > 0) ? (idx - 1) : 0;
            pts[k] = (idx <= N_BINS) ? points[s] : 0.0f;
        }

        float a[4], d[4];
#pragma unroll
        for (int k = 0; k < 4; k++) {
            const int idx = i0 + k;
            a[k] = expf(pv[k]) + 0.001f;
            d[k] = (idx >= 1 && idx <= N_BINS - 1) ? int_len * a[k] : 0.0f;
        }

        float l1 = d[0] + d[1];
        float lsum = l1 + d[2] + d[3];

        float incl = lsum;
#pragma unroll
        for (int o = 1; o < 32; o <<= 1) {
            float u = __shfl_up_sync(0xFFFFFFFFu, incl, o);
            if (t >= o) incl += u;
        }
        const float lane_excl = incl - lsum;

        float ex[4];
        ex[0] = lane_excl;
        ex[1] = lane_excl + d[0];
        ex[2] = lane_excl + l1;
        ex[3] = lane_excl + l1 + d[2];

#pragma unroll
        for (int k = 0; k < 4; k++) {
            const int idx = i0 + k;
            if (idx <= N_BINS)
                sAB[idx] = make_float2(a[k], (b0 + ex[k]) - pts[k] * a[k]);
        }
    }

    // ---- Prefetch first element before the barrier (hides table build).
    const int stride = GRID * TPB;
    int i = blockIdx.x * TPB + t;
    bool have = (i < n4);
    float4 cur;
    if (have) cur = eps[i];

    __syncthreads();

    const float inv_len = 99.0f / 10.0f;

    // ---- Pipelined grid-stride loop: next load in flight while processing.
    while (have) {
        const int inext = i + stride;
        const bool hnext = (inext < n4);
        float4 nxt;
        if (hnext) nxt = eps[inext];   // issue before dependent work below

        float4 r;
        {
            int ix = __float2int_rd(fmaf(cur.x, inv_len, 49.5f)) + 1;
            ix = max(0, min(ix, N_BINS));
            const float2 ab = sAB[ix];
            r.x = fmaf(cur.x, ab.x, ab.y);
        }
        {
            int ix = __float2int_rd(fmaf(cur.y, inv_len, 49.5f)) + 1;
            ix = max(0, min(ix, N_BINS));
            const float2 ab = sAB[ix];
            r.y = fmaf(cur.y, ab.x, ab.y);
        }
        {
            int ix = __float2int_rd(fmaf(cur.z, inv_len, 49.5f)) + 1;
            ix = max(0, min(ix, N_BINS));
            const float2 ab = sAB[ix];
            r.z = fmaf(cur.z, ab.x, ab.y);
        }
        {
            int ix = __float2int_rd(fmaf(cur.w, inv_len, 49.5f)) + 1;
            ix = max(0, min(ix, N_BINS));
            const float2 ab = sAB[ix];
            r.w = fmaf(cur.w, ab.x, ab.y);
        }
        out[i] = r;

        cur = nxt;
        i = inext;
        have = hnext;
    }
}

extern "C" void kernel_launch(void* const* d_in, const int* in_sizes, int n_in,
                              void* d_out, int out_size) {
    const float* eps    = (const float*)d_in[0];   // [4000000]
    const float* p      = (const float*)d_in[1];   // [101]
    const float* b      = (const float*)d_in[2];   // [1]
    const float* points = (const float*)d_in[3];   // [100]
    float* out = (float*)d_out;

    const int n4 = out_size / 4;                   // 1,000,000
    pwl_kernel<<<GRID, TPB>>>((const float4*)eps, p, b, points,
                              (float4*)out, n4);
}